// round 13
// baseline (speedup 1.0000x reference)
#include <cuda_runtime.h>
#include <math.h>

#define UNITS 1024
#define FEAT  1024
#define GCOLS 4096                  // 4 * UNITS gate columns
#define GC4   (GCOLS / 4)           // 1024 float4 columns
#define NBLK  128                   // blocks; each owns 8 float4 cols (32 scalar)
#define KPT   8                     // k-rows per thread (1024 k / 128 kt-groups)

// Scratch (device globals) — complete gate pre-activations, no partials.
__device__ float4 g_z0[GC4];        // x0@W + b       (complete)
__device__ float4 g_z1pre[GC4];     // x1@W + b       (complete)
__device__ float4 g_z1[GC4];        // x1@W + b + h0@U (complete)

__device__ __forceinline__ float sigmoidf_(float x) {
    return 1.0f / (1.0f + expf(-x));
}

__device__ __forceinline__ void f4add(float4& a, const float4& v) {
    a.x += v.x; a.y += v.y; a.z += v.z; a.w += v.w;
}
__device__ __forceinline__ void f4shfl_acc(float4& a, int off, unsigned m) {
    a.x += __shfl_down_sync(m, a.x, off);
    a.y += __shfl_down_sync(m, a.y, off);
    a.z += __shfl_down_sync(m, a.z, off);
    a.w += __shfl_down_sync(m, a.w, off);
}

// ---------------------------------------------------------------------------
// Kernel 1: z0 = x0@W + b and z1pre = x1@W + b, COMPLETE per block.
// 128 blocks x 1024 threads. Block cb owns float4 cols [cb*8, cb*8+8).
// Thread (c = tid&7, kt = tid>>3) accumulates k-rows [kt*8, kt*8+8).
// A warp covers 8 cols x 4 kt-groups: each loaded k-row segment is one
// contiguous 128B line. Reduction: intra-warp shuffles (4 kt-groups) ->
// smem [32 warps][8 cols] -> warp w reduces col w via 32-lane shuffle tree.
// All fixed-order => deterministic.
// ---------------------------------------------------------------------------
__global__ void __launch_bounds__(1024, 1)
k_xw(const float* __restrict__ x, const float* __restrict__ W,
     const float* __restrict__ b) {
    __shared__ float  xs0[FEAT], xs1[FEAT];
    __shared__ float4 red0[32][8];
    __shared__ float4 red1[32][8];
    const int tid  = threadIdx.x;
    const int lane = tid & 31;
    const int wrp  = tid >> 5;
    const int c    = tid & 7;          // local float4 col
    const int kt   = tid >> 3;         // k-group (0..127)
    const int cb   = blockIdx.x;

    for (int i = tid; i < FEAT; i += 1024) {
        xs0[i] = x[i];
        xs1[i] = x[FEAT + i];
    }
    __syncthreads();

    const float4* Wp = reinterpret_cast<const float4*>(W)
                     + (size_t)(kt * KPT) * GC4 + cb * 8 + c;
    float4 a0 = make_float4(0.f, 0.f, 0.f, 0.f);
    float4 a1 = make_float4(0.f, 0.f, 0.f, 0.f);
    #pragma unroll
    for (int kk = 0; kk < KPT; ++kk) {
        const float4 w = Wp[(size_t)kk * GC4];
        const float xa = xs0[kt * KPT + kk];
        const float xb = xs1[kt * KPT + kk];
        a0.x = fmaf(xa, w.x, a0.x); a0.y = fmaf(xa, w.y, a0.y);
        a0.z = fmaf(xa, w.z, a0.z); a0.w = fmaf(xa, w.w, a0.w);
        a1.x = fmaf(xb, w.x, a1.x); a1.y = fmaf(xb, w.y, a1.y);
        a1.z = fmaf(xb, w.z, a1.z); a1.w = fmaf(xb, w.w, a1.w);
    }
    const unsigned m = 0xffffffffu;
    // sum the 4 kt-subgroups inside the warp: lanes {c, c+8, c+16, c+24}
    f4shfl_acc(a0, 16, m); f4shfl_acc(a0, 8, m);
    f4shfl_acc(a1, 16, m); f4shfl_acc(a1, 8, m);
    if (lane < 8) {
        red0[wrp][lane] = a0;
        red1[wrp][lane] = a1;
    }
    __syncthreads();

    // warp w (w<8) reduces local col w across the 32 warps
    if (wrp < 8) {
        float4 v0 = red0[lane][wrp];
        float4 v1 = red1[lane][wrp];
        f4shfl_acc(v0, 16, m); f4shfl_acc(v0, 8, m); f4shfl_acc(v0, 4, m);
        f4shfl_acc(v0, 2, m);  f4shfl_acc(v0, 1, m);
        f4shfl_acc(v1, 16, m); f4shfl_acc(v1, 8, m); f4shfl_acc(v1, 4, m);
        f4shfl_acc(v1, 2, m);  f4shfl_acc(v1, 1, m);
        if (lane == 0) {
            const int col4 = cb * 8 + wrp;
            const float4 bb = reinterpret_cast<const float4*>(b)[col4];
            f4add(v0, bb);
            f4add(v1, bb);
            g_z0[col4]    = v0;
            g_z1pre[col4] = v1;
        }
    }
}

// ---------------------------------------------------------------------------
// Kernel 2: z1 = z1pre + h0@U, COMPLETE per block. Same geometry as k_xw.
// h0 is computed directly: thread u does 3 loads from g_z0 (L2-warm) + gate
// math (c_prev = 0): c0 = sig(zi)*zg, h0 = sig(zo)*c0.
// ---------------------------------------------------------------------------
__global__ void __launch_bounds__(1024, 1)
k_hu(const float* __restrict__ U) {
    __shared__ float  h0s[UNITS];
    __shared__ float4 red[32][8];
    const int tid  = threadIdx.x;
    const int lane = tid & 31;
    const int wrp  = tid >> 5;
    const int c    = tid & 7;
    const int kt   = tid >> 3;
    const int cb   = blockIdx.x;

    {
        const float* z0 = reinterpret_cast<const float*>(g_z0);
        const float zi = z0[tid];
        const float zg = z0[2 * UNITS + tid];
        const float zo = z0[3 * UNITS + tid];
        const float c0 = sigmoidf_(zi) * zg;
        h0s[tid] = sigmoidf_(zo) * c0;
    }
    __syncthreads();

    const float4* Up = reinterpret_cast<const float4*>(U)
                     + (size_t)(kt * KPT) * GC4 + cb * 8 + c;
    float4 a = make_float4(0.f, 0.f, 0.f, 0.f);
    #pragma unroll
    for (int kk = 0; kk < KPT; ++kk) {
        const float4 w = Up[(size_t)kk * GC4];
        const float h = h0s[kt * KPT + kk];
        a.x = fmaf(h, w.x, a.x); a.y = fmaf(h, w.y, a.y);
        a.z = fmaf(h, w.z, a.z); a.w = fmaf(h, w.w, a.w);
    }
    const unsigned m = 0xffffffffu;
    f4shfl_acc(a, 16, m); f4shfl_acc(a, 8, m);
    if (lane < 8) red[wrp][lane] = a;
    __syncthreads();

    if (wrp < 8) {
        float4 v = red[lane][wrp];
        f4shfl_acc(v, 16, m); f4shfl_acc(v, 8, m); f4shfl_acc(v, 4, m);
        f4shfl_acc(v, 2, m);  f4shfl_acc(v, 1, m);
        if (lane == 0) {
            const int col4 = cb * 8 + wrp;
            float4 z = g_z1pre[col4];
            f4add(z, v);
            g_z1[col4] = z;
        }
    }
}

// ---------------------------------------------------------------------------
// Kernel 3: one block, 1024 threads = UNITS. Direct loads of complete z0/z1,
// gate math for t=0/t=1, dense head via deterministic in-block reduction,
// tanh + finite difference, write 4 outputs.
// ---------------------------------------------------------------------------
__global__ void k_final(const float* __restrict__ f,
                        const float* __restrict__ Wd,
                        const float* __restrict__ bd,
                        float* __restrict__ out) {
    __shared__ float red[4][32];
    const int u = threadIdx.x;   // 0..1023
    const float* z0 = reinterpret_cast<const float*>(g_z0);
    const float* z1 = reinterpret_cast<const float*>(g_z1);

    const float c0 = sigmoidf_(z0[u]) * z0[2 * UNITS + u];
    const float h0 = sigmoidf_(z0[3 * UNITS + u]) * c0;

    const float c1 = sigmoidf_(z1[UNITS + u]) * c0
                   + sigmoidf_(z1[u]) * z1[2 * UNITS + u];
    const float h1 = sigmoidf_(z1[3 * UNITS + u]) * c1;

    const float n0 = tanhf(h0);
    const float n1 = tanhf(h1);

    const float wd0 = __ldg(Wd + 2 * u);
    const float wd1 = __ldg(Wd + 2 * u + 1);
    float v0 = n0 * wd0;   // -> h_c[0,0]
    float v1 = n0 * wd1;   // -> h_c[0,1]
    float v2 = n1 * wd0;   // -> h_c[1,0]
    float v3 = n1 * wd1;   // -> h_c[1,1]

    const unsigned m = 0xffffffffu;
    const int lane = u & 31;
    const int wrp  = u >> 5;
    #pragma unroll
    for (int off = 16; off > 0; off >>= 1) {
        v0 += __shfl_down_sync(m, v0, off);
        v1 += __shfl_down_sync(m, v1, off);
        v2 += __shfl_down_sync(m, v2, off);
        v3 += __shfl_down_sync(m, v3, off);
    }
    if (lane == 0) {
        red[0][wrp] = v0; red[1][wrp] = v1; red[2][wrp] = v2; red[3][wrp] = v3;
    }
    __syncthreads();

    if (wrp == 0) {
        float r0 = red[0][lane];
        float r1 = red[1][lane];
        float r2 = red[2][lane];
        float r3 = red[3][lane];
        #pragma unroll
        for (int off = 16; off > 0; off >>= 1) {
            r0 += __shfl_down_sync(m, r0, off);
            r1 += __shfl_down_sync(m, r1, off);
            r2 += __shfl_down_sync(m, r2, off);
            r3 += __shfl_down_sync(m, r3, off);
        }
        if (lane == 0) {
            const float b0 = __ldg(bd + 0);
            const float b1 = __ldg(bd + 1);
            const float hc00 = tanhf(r0 + b0);   // h_c[0,0]
            const float hc01 = tanhf(r1 + b1);   // h_c[0,1]
            const float hc10 = tanhf(r2 + b0);   // h_c[1,0]
            const float hc11 = tanhf(r3 + b1);   // h_c[1,1]
            const float den  = __ldg(f + 1) - __ldg(f + 2);
            out[0] = hc00;                       // h_out
            out[1] = hc01;
            out[2] = (hc00 - hc10) / den;        // H
            out[3] = (hc01 - hc11) / den;
        }
    }
}

// ---------------------------------------------------------------------------
extern "C" void kernel_launch(void* const* d_in, const int* in_sizes, int n_in,
                              void* d_out, int out_size) {
    (void)in_sizes; (void)n_in; (void)out_size;
    const float* x  = (const float*)d_in[0];   // inputs (1, 8192, 1024)
    const float* f  = (const float*)d_in[1];   // f (8192, 1)
    const float* W  = (const float*)d_in[2];   // (1024, 4096)
    const float* U  = (const float*)d_in[3];   // (1024, 4096)
    const float* b  = (const float*)d_in[4];   // (4096,)
    const float* Wd = (const float*)d_in[5];   // (1024, 2)
    const float* bd = (const float*)d_in[6];   // (2,)
    float* out = (float*)d_out;

    k_xw   <<<NBLK, 1024>>>(x, W, b);
    k_hu   <<<NBLK, 1024>>>(U);
    k_final<<<1, 1024>>>(f, Wd, bd, out);
}